// round 1
// baseline (speedup 1.0000x reference)
#include <cuda_runtime.h>

#define DEV_INLINE __device__ __forceinline__

constexpr int C   = 8;
constexpr int K   = 64;
constexpr int D   = 32;
constexpr int NN  = 2048;
constexpr int NPB = 128;   // nodes (=threads) per block

// Scratch (allocation-free: device globals)
__device__ float g_Bm[C * NN];   // raw exp(logq), un-normalized
__device__ float g_Sn[C * C];    // S folded with row-normalizers

struct __align__(16) SmemLayer {
    float w1s[64 * 16];   // s_W1 active columns  [i][j]
    float w1t[64 * 16];   // t_W1 active columns
    float w2s[16 * 64];   // s_W2 passive rows    [r][i]
    float w2t[16 * 64];   // t_W2 passive rows
    float b1s[64], b1t[64];
    float b2s[16], b2t[16];
    float anS[32], anT[32], anE[32];
};

// One inverse layer. AOFF = active-index parity (mask==1 at 2j+AOFF),
// passive indices at 2r+PO. Compile-time parity keeps z[]/h[] in registers.
template <int AOFF>
DEV_INLINE void do_layer(SmemLayer& sm, int tid, int c, int k,
                         const float* __restrict__ sW1, const float* __restrict__ sb1,
                         const float* __restrict__ sW2, const float* __restrict__ sb2,
                         const float* __restrict__ tW1, const float* __restrict__ tb1,
                         const float* __restrict__ tW2, const float* __restrict__ tb2,
                         const float* __restrict__ anS, const float* __restrict__ anT,
                         float z[32], float& ld)
{
    constexpr int PO = 1 - AOFF;
    const size_t lk = (size_t)(c * K + k);
    const float* w1sp = sW1 + lk * 2048;
    const float* w1tp = tW1 + lk * 2048;
    const float* w2sp = sW2 + lk * 2048;
    const float* w2tp = tW2 + lk * 2048;

    __syncthreads();   // previous layer's compute done before overwriting smem

    #pragma unroll
    for (int t = 0; t < 8; t++) {
        int idx = tid + t * NPB;
        int i  = idx >> 4, j  = idx & 15;
        sm.w1s[idx] = __ldg(w1sp + i * 32 + 2 * j + AOFF);
        sm.w1t[idx] = __ldg(w1tp + i * 32 + 2 * j + AOFF);
        int r  = idx >> 6, i2 = idx & 63;
        sm.w2s[idx] = __ldg(w2sp + (2 * r + PO) * 64 + i2);
        sm.w2t[idx] = __ldg(w2tp + (2 * r + PO) * 64 + i2);
    }
    if (tid < 64) {
        sm.b1s[tid] = __ldg(sb1 + lk * 64 + tid);
        sm.b1t[tid] = __ldg(tb1 + lk * 64 + tid);
    } else if (tid < 80) {
        int r = tid - 64;
        sm.b2s[r] = __ldg(sb2 + lk * 32 + 2 * r + PO);
        sm.b2t[r] = __ldg(tb2 + lk * 32 + 2 * r + PO);
    } else if (tid < 112) {
        int d2 = tid - 80;
        float a = __ldg(anS + lk * 32 + d2);
        sm.anS[d2] = a;
        sm.anE[d2] = __expf(-a);
        sm.anT[d2] = __ldg(anT + lk * 32 + d2);
    }
    __syncthreads();

    // ---- ActNorm inverse ----
    float asum = 0.f;
    #pragma unroll
    for (int d = 0; d < 32; d++) {
        z[d] = (z[d] - sm.anT[d]) * sm.anE[d];
        asum += sm.anS[d];
    }
    ld -= asum;

    // active inputs
    float x[16];
    #pragma unroll
    for (int j = 0; j < 16; j++) x[j] = z[2 * j + AOFF];

    const float4* w1s4 = (const float4*)sm.w1s;
    const float4* w1t4 = (const float4*)sm.w1t;
    const float4* w2s4 = (const float4*)sm.w2s;
    const float4* w2t4 = (const float4*)sm.w2t;

    float h[64];

    // ---- s-MLP ----
    #pragma unroll
    for (int i = 0; i < 64; i++) {
        float acc = sm.b1s[i];
        #pragma unroll
        for (int jb = 0; jb < 4; jb++) {
            float4 w = w1s4[i * 4 + jb];
            acc = fmaf(w.x, x[4 * jb + 0], acc);
            acc = fmaf(w.y, x[4 * jb + 1], acc);
            acc = fmaf(w.z, x[4 * jb + 2], acc);
            acc = fmaf(w.w, x[4 * jb + 3], acc);
        }
        h[i] = fmaxf(acc, 0.f);
    }
    float sout[16];
    #pragma unroll
    for (int r = 0; r < 16; r++) {
        float acc = sm.b2s[r];
        #pragma unroll
        for (int ib = 0; ib < 16; ib++) {
            float4 w = w2s4[r * 16 + ib];
            acc = fmaf(w.x, h[4 * ib + 0], acc);
            acc = fmaf(w.y, h[4 * ib + 1], acc);
            acc = fmaf(w.z, h[4 * ib + 2], acc);
            acc = fmaf(w.w, h[4 * ib + 3], acc);
        }
        sout[r] = acc;
    }

    // ---- t-MLP (reuse h) ----
    #pragma unroll
    for (int i = 0; i < 64; i++) {
        float acc = sm.b1t[i];
        #pragma unroll
        for (int jb = 0; jb < 4; jb++) {
            float4 w = w1t4[i * 4 + jb];
            acc = fmaf(w.x, x[4 * jb + 0], acc);
            acc = fmaf(w.y, x[4 * jb + 1], acc);
            acc = fmaf(w.z, x[4 * jb + 2], acc);
            acc = fmaf(w.w, x[4 * jb + 3], acc);
        }
        h[i] = fmaxf(acc, 0.f);
    }
    #pragma unroll
    for (int r = 0; r < 16; r++) {
        float acc = sm.b2t[r];
        #pragma unroll
        for (int ib = 0; ib < 16; ib++) {
            float4 w = w2t4[r * 16 + ib];
            acc = fmaf(w.x, h[4 * ib + 0], acc);
            acc = fmaf(w.y, h[4 * ib + 1], acc);
            acc = fmaf(w.z, h[4 * ib + 2], acc);
            acc = fmaf(w.w, h[4 * ib + 3], acc);
        }
        // z update at passive index + log-det
        float e = __expf(-sout[r]);
        z[2 * r + PO] = (z[2 * r + PO] - acc) * e;
        ld -= sout[r];
    }
}

__global__ void __launch_bounds__(NPB)
flow_kernel(const float* __restrict__ nodes,
            const float* __restrict__ sW1, const float* __restrict__ sb1,
            const float* __restrict__ sW2, const float* __restrict__ sb2,
            const float* __restrict__ tW1, const float* __restrict__ tb1,
            const float* __restrict__ tW2, const float* __restrict__ tb2,
            const float* __restrict__ anS, const float* __restrict__ anT,
            const float* __restrict__ loc, const float* __restrict__ lsc)
{
    __shared__ SmemLayer sm;
    const int tid  = threadIdx.x;
    const int c    = blockIdx.y;
    const int node = blockIdx.x * NPB + tid;

    float z[32];
    const float4* np = (const float4*)(nodes + (size_t)node * 32);
    #pragma unroll
    for (int q = 0; q < 8; q++) {
        float4 v = np[q];
        z[4 * q + 0] = v.x; z[4 * q + 1] = v.y;
        z[4 * q + 2] = v.z; z[4 * q + 3] = v.w;
    }
    float ld = 0.f;

    // layers applied in reverse: 63 (odd parity), 62 (even), ..., 1, 0
    #pragma unroll 1
    for (int k = K - 1; k > 0; k -= 2) {
        do_layer<1>(sm, tid, c, k,     sW1, sb1, sW2, sb2, tW1, tb1, tW2, tb2, anS, anT, z, ld);
        do_layer<0>(sm, tid, c, k - 1, sW1, sb1, sW2, sb2, tW1, tb1, tW2, tb2, anS, anT, z, ld);
    }

    // DiagGaussian log_prob
    float acc = 0.f;
    const float* lp = loc + c * 32;
    const float* sp = lsc + c * 32;
    #pragma unroll
    for (int d = 0; d < 32; d++) {
        float ls = __ldg(sp + d);
        float u  = (z[d] - __ldg(lp + d)) * __expf(-ls);
        acc += ls + 0.5f * u * u;
    }
    // 0.5 * D * log(2*pi) = 16 * 1.8378770664093453
    float logq = ld - 29.406037829f - acc;
    g_Bm[c * NN + node] = __expf(logq);
}

// Fold L1 row-normalizers and softmax-normalized S into one 8x8 matrix.
__global__ void norm_kernel(const float* __restrict__ S_unc)
{
    __shared__ float sh_r[8];
    __shared__ float sh_e[64];
    const int tid = threadIdx.x;          // 256 threads, 8 warps
    const int w = tid >> 5, lane = tid & 31;

    float s = 0.f;
    for (int i = lane; i < NN; i += 32) s += g_Bm[w * NN + i];
    #pragma unroll
    for (int o = 16; o; o >>= 1) s += __shfl_xor_sync(0xffffffffu, s, o);
    if (lane == 0) sh_r[w] = fmaxf(s, 1e-12f);
    if (tid < 64) sh_e[tid] = expf(S_unc[tid]);
    __syncthreads();
    if (tid < 64) {
        float tot = 0.f;
        #pragma unroll
        for (int i = 0; i < 64; i++) tot += sh_e[i];
        int c1 = tid >> 3, c2 = tid & 7;
        g_Sn[tid] = sh_e[tid] / (tot * sh_r[c1] * sh_r[c2]);
    }
}

// out[n1][n2] = sum_{c1} Bm[c1][n1] * (Sn @ Bm)[c1][n2]; 64x64 tiles.
__global__ void __launch_bounds__(256)
out_kernel(float* __restrict__ out)
{
    __shared__ float B1[8][64];
    __shared__ float B2[8][64];
    __shared__ float T2[8][64];
    const int tid = threadIdx.x;
    const int n10 = blockIdx.y * 64;
    const int n20 = blockIdx.x * 64;

    for (int t = tid; t < 512; t += 256) {
        int cc = t >> 6, j = t & 63;
        B1[cc][j] = g_Bm[cc * NN + n10 + j];
        B2[cc][j] = g_Bm[cc * NN + n20 + j];
    }
    __syncthreads();
    if (tid < 64) {
        #pragma unroll
        for (int c1 = 0; c1 < 8; c1++) {
            float a = 0.f;
            #pragma unroll
            for (int c2 = 0; c2 < 8; c2++)
                a = fmaf(g_Sn[c1 * 8 + c2], B2[c2][tid], a);
            T2[c1][tid] = a;
        }
    }
    __syncthreads();

    const int ty = tid >> 4, tx = tid & 15;   // 4 rows x 4 cols per thread
    float bv[4][8], tv[8][4];
    #pragma unroll
    for (int cc = 0; cc < 8; cc++) {
        #pragma unroll
        for (int q = 0; q < 4; q++) {
            bv[q][cc] = B1[cc][ty * 4 + q];
            tv[cc][q] = T2[cc][tx * 4 + q];
        }
    }
    #pragma unroll
    for (int q = 0; q < 4; q++) {
        float4 o = {0.f, 0.f, 0.f, 0.f};
        #pragma unroll
        for (int cc = 0; cc < 8; cc++) {
            o.x = fmaf(bv[q][cc], tv[cc][0], o.x);
            o.y = fmaf(bv[q][cc], tv[cc][1], o.y);
            o.z = fmaf(bv[q][cc], tv[cc][2], o.z);
            o.w = fmaf(bv[q][cc], tv[cc][3], o.w);
        }
        *((float4*)(out + (size_t)(n10 + ty * 4 + q) * NN + n20 + tx * 4)) = o;
    }
}

extern "C" void kernel_launch(void* const* d_in, const int* in_sizes, int n_in,
                              void* d_out, int out_size)
{
    const float* nodes = (const float*)d_in[0];
    const float* sW1   = (const float*)d_in[1];
    const float* sb1   = (const float*)d_in[2];
    const float* sW2   = (const float*)d_in[3];
    const float* sb2   = (const float*)d_in[4];
    const float* tW1   = (const float*)d_in[5];
    const float* tb1   = (const float*)d_in[6];
    const float* tW2   = (const float*)d_in[7];
    const float* tb2   = (const float*)d_in[8];
    const float* anS   = (const float*)d_in[9];
    const float* anT   = (const float*)d_in[10];
    const float* loc   = (const float*)d_in[11];
    const float* lsc   = (const float*)d_in[12];
    const float* S_unc = (const float*)d_in[13];
    float* out = (float*)d_out;

    dim3 fg(NN / NPB, C);
    flow_kernel<<<fg, NPB>>>(nodes, sW1, sb1, sW2, sb2,
                             tW1, tb1, tW2, tb2, anS, anT, loc, lsc);
    norm_kernel<<<1, 256>>>(S_unc);
    dim3 og(NN / 64, NN / 64);
    out_kernel<<<og, 256>>>(out);
}

// round 2
// speedup vs baseline: 3.0449x; 3.0449x over previous
#include <cuda_runtime.h>

#define DEV_INLINE __device__ __forceinline__
typedef unsigned long long ull;

constexpr int C   = 8;
constexpr int K   = 64;
constexpr int NN  = 2048;

__device__ float g_Bm[C * NN];
__device__ float g_Sn[C * C];

// ---------- packed f32x2 helpers (Blackwell fma.rn.f32x2) ----------
DEV_INLINE ull pack2(float lo, float hi) {
    ull r; asm("mov.b64 %0, {%1,%2};" : "=l"(r) : "f"(lo), "f"(hi)); return r;
}
DEV_INLINE void unpack2(ull v, float& lo, float& hi) {
    asm("mov.b64 {%0,%1}, %2;" : "=f"(lo), "=f"(hi) : "l"(v));
}
DEV_INLINE ull ffma2(ull a, ull b, ull c) {
    ull d; asm("fma.rn.f32x2 %0, %1, %2, %3;" : "=l"(d) : "l"(a), "l"(b), "l"(c)); return d;
}
DEV_INLINE ull add2(ull a, ull b) {
    ull d; asm("add.rn.f32x2 %0, %1, %2;" : "=l"(d) : "l"(a), "l"(b)); return d;
}
DEV_INLINE ull mul2(ull a, ull b) {
    ull d; asm("mul.rn.f32x2 %0, %1, %2;" : "=l"(d) : "l"(a), "l"(b)); return d;
}
DEV_INLINE ull neg2(ull a) { return a ^ 0x8000000080000000ULL; }

// ---------- shared layout ----------
constexpr int W2STRIDE = 20;   // floats; 80B rows -> 16B aligned, bank-spread
struct __align__(16) SmemLayer {
    float w1s[64 * 16];          // [i][j] active cols
    float w1t[64 * 16];
    float w2sT[64 * W2STRIDE];   // [i][r] transposed passive rows
    float w2tT[64 * W2STRIDE];
    float b1s[64], b1t[64];
    float b2s[16], b2t[16];      // passive-order, pair-readable
    float anEe[16], anFe[16];    // exp(-s), -t*exp(-s) for even dims
    float anEo[16], anFo[16];    //   ...  for odd dims
    float asum;
};

// coupling on packed active/passive halves (all indices compile-time)
DEV_INLINE void do_coupling(SmemLayer& sm, int half,
                            ull (&act)[8], ull (&pas)[8], float& ld)
{
    ull sacc[8], tacc[8];
    const ulonglong2* b2sp = (const ulonglong2*)sm.b2s;
    const ulonglong2* b2tp = (const ulonglong2*)sm.b2t;
    #pragma unroll
    for (int rr = 0; rr < 4; rr++) {
        ulonglong2 bs = b2sp[rr], bt = b2tp[rr];
        sacc[2*rr]   = half ? 0ULL : bs.x;
        sacc[2*rr+1] = half ? 0ULL : bs.y;
        tacc[2*rr]   = half ? 0ULL : bt.x;
        tacc[2*rr+1] = half ? 0ULL : bt.y;
    }

    #pragma unroll 8
    for (int il = 0; il < 32; il++) {
        const int gi = 2 * il + half;      // even/odd i split across the pair
        const ulonglong2* r1s = (const ulonglong2*)(sm.w1s + gi * 16);
        const ulonglong2* r1t = (const ulonglong2*)(sm.w1t + gi * 16);

        ull as = pack2(sm.b1s[gi], 0.f);
        ull at = pack2(sm.b1t[gi], 0.f);
        #pragma unroll
        for (int q = 0; q < 4; q++) {
            ulonglong2 ws = r1s[q], wt = r1t[q];
            as = ffma2(ws.x, act[2*q],   as);
            at = ffma2(wt.x, act[2*q],   at);
            as = ffma2(ws.y, act[2*q+1], as);
            at = ffma2(wt.y, act[2*q+1], at);
        }
        float l0, l1, m0, m1;
        unpack2(as, l0, l1);
        unpack2(at, m0, m1);
        float hs = fmaxf(l0 + l1, 0.f);
        float ht = fmaxf(m0 + m1, 0.f);
        ull hh_s = pack2(hs, hs);
        ull hh_t = pack2(ht, ht);

        const ulonglong2* r2s = (const ulonglong2*)(sm.w2sT + gi * W2STRIDE);
        const ulonglong2* r2t = (const ulonglong2*)(sm.w2tT + gi * W2STRIDE);
        #pragma unroll
        for (int q = 0; q < 4; q++) {
            ulonglong2 ws = r2s[q], wt = r2t[q];
            sacc[2*q]   = ffma2(ws.x, hh_s, sacc[2*q]);
            tacc[2*q]   = ffma2(wt.x, hh_t, tacc[2*q]);
            sacc[2*q+1] = ffma2(ws.y, hh_s, sacc[2*q+1]);
            tacc[2*q+1] = ffma2(wt.y, hh_t, tacc[2*q+1]);
        }
    }

    // butterfly: combine partner's half of the hidden sum
    #pragma unroll
    for (int rr = 0; rr < 8; rr++) {
        sacc[rr] = add2(sacc[rr], __shfl_xor_sync(0xffffffffu, sacc[rr], 1));
        tacc[rr] = add2(tacc[rr], __shfl_xor_sync(0xffffffffu, tacc[rr], 1));
    }

    // passive update + logdet
    #pragma unroll
    for (int rr = 0; rr < 8; rr++) {
        float s0, s1;
        unpack2(sacc[rr], s0, s1);
        ld -= (s0 + s1);
        ull e2 = pack2(__expf(-s0), __expf(-s1));
        ull nt = neg2(mul2(tacc[rr], e2));
        pas[rr] = ffma2(pas[rr], e2, nt);
    }
}

template <int AOFF>
DEV_INLINE void do_layer(SmemLayer& sm, int tid, int half, size_t lk,
                         const float* __restrict__ sW1, const float* __restrict__ sb1,
                         const float* __restrict__ sW2, const float* __restrict__ sb2,
                         const float* __restrict__ tW1, const float* __restrict__ tb1,
                         const float* __restrict__ tW2, const float* __restrict__ tb2,
                         const float* __restrict__ anS, const float* __restrict__ anT,
                         ull (&ze2)[8], ull (&zo2)[8], float& ld)
{
    constexpr int PO = 1 - AOFF;
    const float* w1sp = sW1 + lk * 2048;
    const float* w1tp = tW1 + lk * 2048;
    const float* w2sp = sW2 + lk * 2048;
    const float* w2tp = tW2 + lk * 2048;

    __syncthreads();

    #pragma unroll
    for (int t = 0; t < 8; t++) {
        int idx = tid + t * 128;
        int i = idx >> 4, j = idx & 15;
        sm.w1s[idx] = __ldg(w1sp + i * 32 + 2 * j + AOFF);
        sm.w1t[idx] = __ldg(w1tp + i * 32 + 2 * j + AOFF);
        int i2 = idx & 63, r = idx >> 6;
        sm.w2sT[i2 * W2STRIDE + r] = __ldg(w2sp + (2 * r + PO) * 64 + i2);
        sm.w2tT[i2 * W2STRIDE + r] = __ldg(w2tp + (2 * r + PO) * 64 + i2);
    }
    if (tid < 64) {
        sm.b1s[tid] = __ldg(sb1 + lk * 64 + tid);
        sm.b1t[tid] = __ldg(tb1 + lk * 64 + tid);
    } else if (tid < 80) {
        int r = tid - 64;
        sm.b2s[r] = __ldg(sb2 + lk * 32 + 2 * r + PO);
    } else if (tid < 96) {
        int r = tid - 80;
        sm.b2t[r] = __ldg(tb2 + lk * 32 + 2 * r + PO);
    } else {
        int d = tid - 96;
        float a  = __ldg(anS + lk * 32 + d);
        float tt = __ldg(anT + lk * 32 + d);
        float e = __expf(-a);
        float f = -tt * e;
        if (d & 1) { sm.anEo[d >> 1] = e; sm.anFo[d >> 1] = f; }
        else       { sm.anEe[d >> 1] = e; sm.anFe[d >> 1] = f; }
        float s = a;
        #pragma unroll
        for (int o = 16; o; o >>= 1) s += __shfl_xor_sync(0xffffffffu, s, o);
        if (d == 0) sm.asum = s;
    }
    __syncthreads();

    // ActNorm inverse on packed halves
    const ulonglong2* Ee = (const ulonglong2*)sm.anEe;
    const ulonglong2* Fe = (const ulonglong2*)sm.anFe;
    const ulonglong2* Eo = (const ulonglong2*)sm.anEo;
    const ulonglong2* Fo = (const ulonglong2*)sm.anFo;
    #pragma unroll
    for (int q = 0; q < 4; q++) {
        ulonglong2 e = Ee[q], f = Fe[q];
        ze2[2*q]   = ffma2(ze2[2*q],   e.x, f.x);
        ze2[2*q+1] = ffma2(ze2[2*q+1], e.y, f.y);
        e = Eo[q]; f = Fo[q];
        zo2[2*q]   = ffma2(zo2[2*q],   e.x, f.x);
        zo2[2*q+1] = ffma2(zo2[2*q+1], e.y, f.y);
    }
    ld -= sm.asum;

    if constexpr (AOFF == 0) do_coupling(sm, half, ze2, zo2, ld);
    else                     do_coupling(sm, half, zo2, ze2, ld);
}

__global__ void __launch_bounds__(128, 2)
flow_kernel(const float* __restrict__ nodes,
            const float* __restrict__ sW1, const float* __restrict__ sb1,
            const float* __restrict__ sW2, const float* __restrict__ sb2,
            const float* __restrict__ tW1, const float* __restrict__ tb1,
            const float* __restrict__ tW2, const float* __restrict__ tb2,
            const float* __restrict__ anS, const float* __restrict__ anT,
            const float* __restrict__ loc, const float* __restrict__ lsc)
{
    __shared__ SmemLayer sm;
    const int tid  = threadIdx.x;
    const int half = tid & 1;            // pair-split over hidden units
    const int c    = blockIdx.y;
    const int node = blockIdx.x * 64 + (tid >> 1);

    // z packed by parity: ze2 = even dims, zo2 = odd dims (pairs of consecutive)
    ull ze2[8], zo2[8];
    const float4* np = (const float4*)(nodes + (size_t)node * 32);
    #pragma unroll
    for (int q = 0; q < 8; q++) {
        float4 v = np[q];
        ze2[q] = pack2(v.x, v.z);
        zo2[q] = pack2(v.y, v.w);
    }
    float ld = 0.f;

    #pragma unroll 1
    for (int k = K - 1; k > 0; k -= 2) {
        do_layer<1>(sm, tid, half, (size_t)(c * K + k),
                    sW1, sb1, sW2, sb2, tW1, tb1, tW2, tb2, anS, anT, ze2, zo2, ld);
        do_layer<0>(sm, tid, half, (size_t)(c * K + k - 1),
                    sW1, sb1, sW2, sb2, tW1, tb1, tW2, tb2, anS, anT, ze2, zo2, ld);
    }

    // DiagGaussian log_prob
    float acc = 0.f;
    const float* lp = loc + c * 32;
    const float* sp = lsc + c * 32;
    #pragma unroll
    for (int q = 0; q < 8; q++) {
        float e0, e1, o0, o1;
        unpack2(ze2[q], e0, e1);   // dims 4q, 4q+2
        unpack2(zo2[q], o0, o1);   // dims 4q+1, 4q+3
        float z4[4] = {e0, o0, e1, o1};
        #pragma unroll
        for (int b = 0; b < 4; b++) {
            int d = 4 * q + b;
            float ls = __ldg(sp + d);
            float u  = (z4[b] - __ldg(lp + d)) * __expf(-ls);
            acc += ls + 0.5f * u * u;
        }
    }
    float logq = ld - 29.406037829f - acc;   // 16 * log(2*pi)
    if (half == 0) g_Bm[c * NN + node] = __expf(logq);
}

// Fold L1 row-normalizers and softmax-normalized S into one 8x8 matrix.
__global__ void norm_kernel(const float* __restrict__ S_unc)
{
    __shared__ float sh_r[8];
    __shared__ float sh_e[64];
    const int tid = threadIdx.x;
    const int w = tid >> 5, lane = tid & 31;

    float s = 0.f;
    for (int i = lane; i < NN; i += 32) s += g_Bm[w * NN + i];
    #pragma unroll
    for (int o = 16; o; o >>= 1) s += __shfl_xor_sync(0xffffffffu, s, o);
    if (lane == 0) sh_r[w] = fmaxf(s, 1e-12f);
    if (tid < 64) sh_e[tid] = expf(S_unc[tid]);
    __syncthreads();
    if (tid < 64) {
        float tot = 0.f;
        #pragma unroll
        for (int i = 0; i < 64; i++) tot += sh_e[i];
        int c1 = tid >> 3, c2 = tid & 7;
        g_Sn[tid] = sh_e[tid] / (tot * sh_r[c1] * sh_r[c2]);
    }
}

__global__ void __launch_bounds__(256)
out_kernel(float* __restrict__ out)
{
    __shared__ float B1[8][64];
    __shared__ float B2[8][64];
    __shared__ float T2[8][64];
    const int tid = threadIdx.x;
    const int n10 = blockIdx.y * 64;
    const int n20 = blockIdx.x * 64;

    for (int t = tid; t < 512; t += 256) {
        int cc = t >> 6, j = t & 63;
        B1[cc][j] = g_Bm[cc * NN + n10 + j];
        B2[cc][j] = g_Bm[cc * NN + n20 + j];
    }
    __syncthreads();
    if (tid < 64) {
        #pragma unroll
        for (int c1 = 0; c1 < 8; c1++) {
            float a = 0.f;
            #pragma unroll
            for (int c2 = 0; c2 < 8; c2++)
                a = fmaf(g_Sn[c1 * 8 + c2], B2[c2][tid], a);
            T2[c1][tid] = a;
        }
    }
    __syncthreads();

    const int ty = tid >> 4, tx = tid & 15;
    float bv[4][8], tv[8][4];
    #pragma unroll
    for (int cc = 0; cc < 8; cc++) {
        #pragma unroll
        for (int q = 0; q < 4; q++) {
            bv[q][cc] = B1[cc][ty * 4 + q];
            tv[cc][q] = T2[cc][tx * 4 + q];
        }
    }
    #pragma unroll
    for (int q = 0; q < 4; q++) {
        float4 o = {0.f, 0.f, 0.f, 0.f};
        #pragma unroll
        for (int cc = 0; cc < 8; cc++) {
            o.x = fmaf(bv[q][cc], tv[cc][0], o.x);
            o.y = fmaf(bv[q][cc], tv[cc][1], o.y);
            o.z = fmaf(bv[q][cc], tv[cc][2], o.z);
            o.w = fmaf(bv[q][cc], tv[cc][3], o.w);
        }
        *((float4*)(out + (size_t)(n10 + ty * 4 + q) * NN + n20 + tx * 4)) = o;
    }
}

extern "C" void kernel_launch(void* const* d_in, const int* in_sizes, int n_in,
                              void* d_out, int out_size)
{
    const float* nodes = (const float*)d_in[0];
    const float* sW1   = (const float*)d_in[1];
    const float* sb1   = (const float*)d_in[2];
    const float* sW2   = (const float*)d_in[3];
    const float* sb2   = (const float*)d_in[4];
    const float* tW1   = (const float*)d_in[5];
    const float* tb1   = (const float*)d_in[6];
    const float* tW2   = (const float*)d_in[7];
    const float* tb2   = (const float*)d_in[8];
    const float* anS   = (const float*)d_in[9];
    const float* anT   = (const float*)d_in[10];
    const float* loc   = (const float*)d_in[11];
    const float* lsc   = (const float*)d_in[12];
    const float* S_unc = (const float*)d_in[13];
    float* out = (float*)d_out;

    dim3 fg(NN / 64, C);                 // 32 x 8 = 256 blocks, 2 threads/node
    flow_kernel<<<fg, 128>>>(nodes, sW1, sb1, sW2, sb2,
                             tW1, tb1, tW2, tb2, anS, anT, loc, lsc);
    norm_kernel<<<1, 256>>>(S_unc);
    dim3 og(NN / 64, NN / 64);
    out_kernel<<<og, 256>>>(out);
}

// round 3
// speedup vs baseline: 3.0632x; 1.0060x over previous
#include <cuda_runtime.h>

#define DEV_INLINE __device__ __forceinline__
typedef unsigned long long ull;

constexpr int C  = 8;
constexpr int K  = 64;
constexpr int NN = 2048;

// ---- per-(c,k) repacked blob layout (floats) ----
constexpr int BLOB = 5632;               // 22528 B, 1408 x 16B chunks, /128 thr = 11
constexpr int W1S = 0;                   // [64][20] stride-padded, cols 0..15 valid
constexpr int W1T = 1280;
constexpr int W2S = 2560;                // transposed [i][r], stride 20
constexpr int W2T = 3840;
constexpr int B1S = 5120, B1T = 5184;
constexpr int B2S = 5248, B2T = 5264;    // passive order
constexpr int ANE = 5280;                // [act 16 | pas 16] exp(-s)
constexpr int ANF = 5312;                // [act 16 | pas 16] -t*exp(-s)
constexpr int ASUM = 5344;

__device__ float g_blob[C * K * BLOB];   // ~11.5 MB scratch
__device__ float g_Bm[C * NN];
__device__ float g_Sn[C * C];

// ---------- packed f32x2 helpers ----------
DEV_INLINE ull pack2(float lo, float hi) {
    ull r; asm("mov.b64 %0, {%1,%2};" : "=l"(r) : "f"(lo), "f"(hi)); return r;
}
DEV_INLINE void unpack2(ull v, float& lo, float& hi) {
    asm("mov.b64 {%0,%1}, %2;" : "=f"(lo), "=f"(hi) : "l"(v));
}
DEV_INLINE ull ffma2(ull a, ull b, ull c) {
    ull d; asm("fma.rn.f32x2 %0, %1, %2, %3;" : "=l"(d) : "l"(a), "l"(b), "l"(c)); return d;
}
DEV_INLINE ull add2(ull a, ull b) {
    ull d; asm("add.rn.f32x2 %0, %1, %2;" : "=l"(d) : "l"(a), "l"(b)); return d;
}
DEV_INLINE ull mul2(ull a, ull b) {
    ull d; asm("mul.rn.f32x2 %0, %1, %2;" : "=l"(d) : "l"(a), "l"(b)); return d;
}
DEV_INLINE ull neg2(ull a) { return a ^ 0x8000000080000000ULL; }

// ---------- cp.async staging ----------
DEV_INLINE void stage(float* sdst, const float* gsrc, int tid) {
    unsigned sa = (unsigned)__cvta_generic_to_shared(sdst);
    #pragma unroll
    for (int i = 0; i < 11; i++) {
        int ch = tid + i * 128;
        asm volatile("cp.async.cg.shared.global [%0], [%1], 16;"
                     :: "r"(sa + ch * 16), "l"(gsrc + ch * 4));
    }
    asm volatile("cp.async.commit_group;");
}
DEV_INLINE void wait_stage() {
    asm volatile("cp.async.wait_group 0;" ::: "memory");
}

// ---------- repack: gather/compact/transpose weights once ----------
__global__ void __launch_bounds__(128)
repack_kernel(const float* __restrict__ sW1, const float* __restrict__ sb1,
              const float* __restrict__ sW2, const float* __restrict__ sb2,
              const float* __restrict__ tW1, const float* __restrict__ tb1,
              const float* __restrict__ tW2, const float* __restrict__ tb2,
              const float* __restrict__ anS, const float* __restrict__ anT)
{
    const int ck = blockIdx.x;          // c*64+k
    const int k = ck & 63;
    const int A = k & 1, PO = 1 - A;    // active parity / passive parity
    float* B = g_blob + (size_t)ck * BLOB;
    const int tid = threadIdx.x;
    const size_t wo = (size_t)ck * 2048;

    for (int idx = tid; idx < 1024; idx += 128) {
        int i = idx >> 4, j = idx & 15;
        B[W1S + i * 20 + j] = sW1[wo + i * 32 + 2 * j + A];
        B[W1T + i * 20 + j] = tW1[wo + i * 32 + 2 * j + A];
        B[W2S + i * 20 + j] = sW2[wo + (2 * j + PO) * 64 + i];
        B[W2T + i * 20 + j] = tW2[wo + (2 * j + PO) * 64 + i];
    }
    if (tid < 64) {
        B[B1S + tid] = sb1[ck * 64 + tid];
        B[B1T + tid] = tb1[ck * 64 + tid];
    } else if (tid < 80) {
        int r = tid - 64;
        B[B2S + r] = sb2[ck * 32 + 2 * r + PO];
        B[B2T + r] = tb2[ck * 32 + 2 * r + PO];
    } else if (tid < 112) {
        int q = tid - 80;               // 0..31: [act 16 | pas 16]
        int dim = (q < 16) ? (2 * q + A) : (2 * (q - 16) + PO);
        float a = anS[ck * 32 + dim];
        float t = anT[ck * 32 + dim];
        float e = __expf(-a);
        B[ANE + q] = e;
        B[ANF + q] = -t * e;
    } else if (tid == 112) {
        float s = 0.f;
        for (int d = 0; d < 32; d++) s += anS[ck * 32 + d];
        B[ASUM] = s;
    }
}

// ---------- one inverse layer: quarter-split hidden, 2 nodes/thread ----------
DEV_INLINE void layer_compute(const float* __restrict__ sb, int q,
                              ull (&a0)[8], ull (&p0)[8],
                              ull (&a1)[8], ull (&p1)[8],
                              float& ld0, float& ld1)
{
    // ActNorm inverse (E/F stored in act|pas order)
    const ull* E = (const ull*)(sb + ANE);
    const ull* F = (const ull*)(sb + ANF);
    #pragma unroll
    for (int j = 0; j < 8; j++) {
        ull e = E[j], f = F[j];
        a0[j] = ffma2(a0[j], e, f);
        a1[j] = ffma2(a1[j], e, f);
        ull e2 = E[8 + j], f2 = F[8 + j];
        p0[j] = ffma2(p0[j], e2, f2);
        p1[j] = ffma2(p1[j], e2, f2);
    }
    float asum = sb[ASUM];
    ld0 -= asum; ld1 -= asum;

    // accumulators (16 outputs as 8 packed pairs) per node
    ull s0[8], t0[8], s1[8], t1[8];
    const ull* b2s = (const ull*)(sb + B2S);
    const ull* b2t = (const ull*)(sb + B2T);
    #pragma unroll
    for (int j = 0; j < 8; j++) {
        ull bs = (q == 0) ? b2s[j] : 0ULL;
        ull bt = (q == 0) ? b2t[j] : 0ULL;
        s0[j] = bs; s1[j] = bs; t0[j] = bt; t1[j] = bt;
    }

    #pragma unroll 4
    for (int il = 0; il < 16; il++) {
        const int gi = il * 4 + q;                  // this thread's hidden unit
        const ull* r1s = (const ull*)(sb + W1S + gi * 20);
        const ull* r1t = (const ull*)(sb + W1T + gi * 20);
        float b1sv = sb[B1S + gi], b1tv = sb[B1T + gi];
        ull as0 = pack2(b1sv, 0.f), as1 = pack2(b1sv, 0.f);
        ull at0 = pack2(b1tv, 0.f), at1 = pack2(b1tv, 0.f);
        #pragma unroll
        for (int j = 0; j < 8; j++) {
            ull ws = r1s[j], wt = r1t[j];
            as0 = ffma2(ws, a0[j], as0);
            as1 = ffma2(ws, a1[j], as1);
            at0 = ffma2(wt, a0[j], at0);
            at1 = ffma2(wt, a1[j], at1);
        }
        float x, y;
        unpack2(as0, x, y); float hs0 = fmaxf(x + y, 0.f);
        unpack2(as1, x, y); float hs1 = fmaxf(x + y, 0.f);
        unpack2(at0, x, y); float ht0 = fmaxf(x + y, 0.f);
        unpack2(at1, x, y); float ht1 = fmaxf(x + y, 0.f);
        ull hs0p = pack2(hs0, hs0), hs1p = pack2(hs1, hs1);
        ull ht0p = pack2(ht0, ht0), ht1p = pack2(ht1, ht1);

        const ull* r2s = (const ull*)(sb + W2S + gi * 20);
        const ull* r2t = (const ull*)(sb + W2T + gi * 20);
        #pragma unroll
        for (int j = 0; j < 8; j++) {
            ull ws = r2s[j], wt = r2t[j];
            s0[j] = ffma2(ws, hs0p, s0[j]);
            s1[j] = ffma2(ws, hs1p, s1[j]);
            t0[j] = ffma2(wt, ht0p, t0[j]);
            t1[j] = ffma2(wt, ht1p, t1[j]);
        }
    }

    // butterfly over the 4 quarter-threads (lanes q, q^1, q^2)
    #pragma unroll
    for (int j = 0; j < 8; j++) {
        s0[j] = add2(s0[j], __shfl_xor_sync(0xffffffffu, s0[j], 1));
        s0[j] = add2(s0[j], __shfl_xor_sync(0xffffffffu, s0[j], 2));
        t0[j] = add2(t0[j], __shfl_xor_sync(0xffffffffu, t0[j], 1));
        t0[j] = add2(t0[j], __shfl_xor_sync(0xffffffffu, t0[j], 2));
        s1[j] = add2(s1[j], __shfl_xor_sync(0xffffffffu, s1[j], 1));
        s1[j] = add2(s1[j], __shfl_xor_sync(0xffffffffu, s1[j], 2));
        t1[j] = add2(t1[j], __shfl_xor_sync(0xffffffffu, t1[j], 1));
        t1[j] = add2(t1[j], __shfl_xor_sync(0xffffffffu, t1[j], 2));
    }

    // passive update + logdet (redundant across quarters, consistent)
    #pragma unroll
    for (int j = 0; j < 8; j++) {
        float sa, sbv;
        unpack2(s0[j], sa, sbv);
        ld0 -= (sa + sbv);
        ull e2 = pack2(__expf(-sa), __expf(-sbv));
        p0[j] = ffma2(p0[j], e2, neg2(mul2(t0[j], e2)));
        unpack2(s1[j], sa, sbv);
        ld1 -= (sa + sbv);
        e2 = pack2(__expf(-sa), __expf(-sbv));
        p1[j] = ffma2(p1[j], e2, neg2(mul2(t1[j], e2)));
    }
}

__global__ void __launch_bounds__(128)
flow_kernel(const float* __restrict__ nodes,
            const float* __restrict__ loc, const float* __restrict__ lsc)
{
    __shared__ __align__(16) float sbuf[2][BLOB];
    const int tid  = threadIdx.x;
    const int q    = tid & 3;            // quarter of hidden units
    const int slot = tid >> 2;           // 0..31
    const int c    = blockIdx.y;
    const int n0   = blockIdx.x * 64 + slot;
    const int n1   = n0 + 32;

    // z packed by parity: ze[q]=(dims 4q,4q+2), zo[q]=(4q+1,4q+3)
    ull ze0[8], zo0[8], ze1[8], zo1[8];
    {
        const float4* np = (const float4*)(nodes + (size_t)n0 * 32);
        #pragma unroll
        for (int j = 0; j < 8; j++) {
            float4 v = np[j];
            ze0[j] = pack2(v.x, v.z); zo0[j] = pack2(v.y, v.w);
        }
        np = (const float4*)(nodes + (size_t)n1 * 32);
        #pragma unroll
        for (int j = 0; j < 8; j++) {
            float4 v = np[j];
            ze1[j] = pack2(v.x, v.z); zo1[j] = pack2(v.y, v.w);
        }
    }
    float ld0 = 0.f, ld1 = 0.f;

    const float* gb = g_blob + (size_t)(c * 64) * BLOB;

    stage(sbuf[0], gb + (size_t)63 * BLOB, tid);
    wait_stage();
    __syncthreads();

    #pragma unroll 1
    for (int k = 63; k > 0; k -= 2) {
        stage(sbuf[1], gb + (size_t)(k - 1) * BLOB, tid);
        // layer k (odd): active = odd dims
        layer_compute(sbuf[0], q, zo0, ze0, zo1, ze1, ld0, ld1);
        wait_stage();
        __syncthreads();
        if (k >= 3) stage(sbuf[0], gb + (size_t)(k - 2) * BLOB, tid);
        // layer k-1 (even): active = even dims
        layer_compute(sbuf[1], q, ze0, zo0, ze1, zo1, ld0, ld1);
        wait_stage();
        __syncthreads();
    }

    // DiagGaussian log_prob
    float acc0 = 0.f, acc1 = 0.f;
    const float* lp = loc + c * 32;
    const float* sp = lsc + c * 32;
    #pragma unroll
    for (int j = 0; j < 8; j++) {
        float e0, e1, o0, o1;
        float z40[4], z41[4];
        unpack2(ze0[j], e0, e1); unpack2(zo0[j], o0, o1);
        z40[0] = e0; z40[1] = o0; z40[2] = e1; z40[3] = o1;
        unpack2(ze1[j], e0, e1); unpack2(zo1[j], o0, o1);
        z41[0] = e0; z41[1] = o0; z41[2] = e1; z41[3] = o1;
        #pragma unroll
        for (int b = 0; b < 4; b++) {
            int d = 4 * j + b;
            float ls = __ldg(sp + d);
            float es = __expf(-ls);
            float u0 = (z40[b] - __ldg(lp + d)) * es;
            float u1 = (z41[b] - __ldg(lp + d)) * es;
            acc0 += ls + 0.5f * u0 * u0;
            acc1 += ls + 0.5f * u1 * u1;
        }
    }
    if (q == 0) {
        g_Bm[c * NN + n0] = __expf(ld0 - 29.406037829f - acc0);
        g_Bm[c * NN + n1] = __expf(ld1 - 29.406037829f - acc1);
    }
}

// Fold L1 row-normalizers and softmax-normalized S into one 8x8 matrix.
__global__ void norm_kernel(const float* __restrict__ S_unc)
{
    __shared__ float sh_r[8];
    __shared__ float sh_e[64];
    const int tid = threadIdx.x;
    const int w = tid >> 5, lane = tid & 31;

    float s = 0.f;
    for (int i = lane; i < NN; i += 32) s += g_Bm[w * NN + i];
    #pragma unroll
    for (int o = 16; o; o >>= 1) s += __shfl_xor_sync(0xffffffffu, s, o);
    if (lane == 0) sh_r[w] = fmaxf(s, 1e-12f);
    if (tid < 64) sh_e[tid] = expf(S_unc[tid]);
    __syncthreads();
    if (tid < 64) {
        float tot = 0.f;
        #pragma unroll
        for (int i = 0; i < 64; i++) tot += sh_e[i];
        int c1 = tid >> 3, c2 = tid & 7;
        g_Sn[tid] = sh_e[tid] / (tot * sh_r[c1] * sh_r[c2]);
    }
}

__global__ void __launch_bounds__(256)
out_kernel(float* __restrict__ out)
{
    __shared__ float B1[8][64];
    __shared__ float B2[8][64];
    __shared__ float T2[8][64];
    const int tid = threadIdx.x;
    const int n10 = blockIdx.y * 64;
    const int n20 = blockIdx.x * 64;

    for (int t = tid; t < 512; t += 256) {
        int cc = t >> 6, j = t & 63;
        B1[cc][j] = g_Bm[cc * NN + n10 + j];
        B2[cc][j] = g_Bm[cc * NN + n20 + j];
    }
    __syncthreads();
    if (tid < 64) {
        #pragma unroll
        for (int c1 = 0; c1 < 8; c1++) {
            float a = 0.f;
            #pragma unroll
            for (int c2 = 0; c2 < 8; c2++)
                a = fmaf(g_Sn[c1 * 8 + c2], B2[c2][tid], a);
            T2[c1][tid] = a;
        }
    }
    __syncthreads();

    const int ty = tid >> 4, tx = tid & 15;
    float bv[4][8], tv[8][4];
    #pragma unroll
    for (int cc = 0; cc < 8; cc++) {
        #pragma unroll
        for (int p = 0; p < 4; p++) {
            bv[p][cc] = B1[cc][ty * 4 + p];
            tv[cc][p] = T2[cc][tx * 4 + p];
        }
    }
    #pragma unroll
    for (int p = 0; p < 4; p++) {
        float4 o = {0.f, 0.f, 0.f, 0.f};
        #pragma unroll
        for (int cc = 0; cc < 8; cc++) {
            o.x = fmaf(bv[p][cc], tv[cc][0], o.x);
            o.y = fmaf(bv[p][cc], tv[cc][1], o.y);
            o.z = fmaf(bv[p][cc], tv[cc][2], o.z);
            o.w = fmaf(bv[p][cc], tv[cc][3], o.w);
        }
        *((float4*)(out + (size_t)(n10 + ty * 4 + p) * NN + n20 + tx * 4)) = o;
    }
}

extern "C" void kernel_launch(void* const* d_in, const int* in_sizes, int n_in,
                              void* d_out, int out_size)
{
    const float* nodes = (const float*)d_in[0];
    const float* sW1   = (const float*)d_in[1];
    const float* sb1   = (const float*)d_in[2];
    const float* sW2   = (const float*)d_in[3];
    const float* sb2   = (const float*)d_in[4];
    const float* tW1   = (const float*)d_in[5];
    const float* tb1   = (const float*)d_in[6];
    const float* tW2   = (const float*)d_in[7];
    const float* tb2   = (const float*)d_in[8];
    const float* anS   = (const float*)d_in[9];
    const float* anT   = (const float*)d_in[10];
    const float* loc   = (const float*)d_in[11];
    const float* lsc   = (const float*)d_in[12];
    const float* S_unc = (const float*)d_in[13];
    float* out = (float*)d_out;

    repack_kernel<<<C * K, 128>>>(sW1, sb1, sW2, sb2, tW1, tb1, tW2, tb2, anS, anT);
    dim3 fg(NN / 64, C);                 // 32 x 8 = 256 blocks
    flow_kernel<<<fg, 128>>>(nodes, loc, lsc);
    norm_kernel<<<1, 256>>>(S_unc);
    dim3 og(NN / 64, NN / 64);
    out_kernel<<<og, 256>>>(out);
}